// round 15
// baseline (speedup 1.0000x reference)
#include <cuda_runtime.h>
#include <math.h>

// Problem constants (fixed by reference)
#define VOCAB 100000
#define DIM   128
#define BATCH 16384
#define CTX   10
#define NEG   5

#define WARPS_PER_BLOCK 4
#define THREADS (WARPS_PER_BLOCK * 32)              // 128
#define ELEMS_PER_WARP 4
#define NUM_BLOCKS (BATCH / (WARPS_PER_BLOCK * ELEMS_PER_WARP))   // 1024: single wave
#define ROWS_PER_ELEM 16                            // 10 ctx + 1 pos + 5 neg

// Scratch (no cudaMalloc allowed)
__device__ double       g_accum  = 0.0;
__device__ unsigned int g_ticket = 0;

__device__ __forceinline__ float log_sigmoid(float x) {
    // stable: min(x,0) - log1p(exp(-|x|))
    return fminf(x, 0.0f) - log1pf(expf(-fabsf(x)));
}

// Asymmetric L2 policy (measured-best): pin u-table, stream w-table.
__device__ __forceinline__ unsigned long long make_policy_keep() {
    unsigned long long pol;
    asm("createpolicy.fractional.L2::evict_last.b64 %0, 1.0;" : "=l"(pol));
    return pol;
}
__device__ __forceinline__ unsigned long long make_policy_stream() {
    unsigned long long pol;
    asm("createpolicy.fractional.L2::evict_first.b64 %0, 1.0;" : "=l"(pol));
    return pol;
}

// 16B async copy gmem->smem, bypassing registers (deep MLP without reg cost).
__device__ __forceinline__ void cp_async16(unsigned dst_smem, const float4* src,
                                           unsigned long long pol) {
    asm volatile("cp.async.cg.shared.global.L2::cache_hint [%0], [%1], 16, %2;"
                 :: "r"(dst_smem), "l"(src), "l"(pol) : "memory");
}
__device__ __forceinline__ void cp_async_commit() {
    asm volatile("cp.async.commit_group;" ::: "memory");
}
__device__ __forceinline__ void cp_async_wait_all() {
    asm volatile("cp.async.wait_group 0;" ::: "memory");
}

__global__ __launch_bounds__(THREADS)
void cbow_loss_fused(const int* __restrict__ pos_u,   // [B, CTX]
                     const int* __restrict__ pos_w,   // [B]
                     const int* __restrict__ neg_w,   // [B, NEG]
                     const float4* __restrict__ u_w,  // [VOCAB, 32] as float4
                     const float4* __restrict__ w_w,  // [VOCAB, 32] as float4
                     float* __restrict__ out)
{
    // Per-warp staging: 16 rows x 512B. Lane l owns bytes [16l,16l+16) of each
    // row (the float4 it will read back) -> same-thread cp.async, no syncwarp.
    __shared__ float4 buf[WARPS_PER_BLOCK][ROWS_PER_ELEM][32];   // 32 KB

    const int warp = threadIdx.x >> 5;
    const int lane = threadIdx.x & 31;
    const int b0 = (blockIdx.x * WARPS_PER_BLOCK + warp) * ELEMS_PER_WARP;

    const unsigned long long pol_keep   = make_policy_keep();
    const unsigned long long pol_stream = make_policy_stream();

    const unsigned dst0 =
        (unsigned)__cvta_generic_to_shared(&buf[warp][0][lane]);

    float ls = 0.0f;   // lane0 accumulates logsigmoid terms

    #pragma unroll 1
    for (int e = 0; e < ELEMS_PER_WARP; ++e) {
        const int b = b0 + e;
        const int* pu = pos_u + b * CTX;
        const int* nw = neg_w + b * NEG;

        // ---- issue ALL 16 row copies: 8KB in flight per warp ----
        #pragma unroll
        for (int c = 0; c < CTX; ++c) {
            int idx = __ldg(pu + c);
            cp_async16(dst0 + c * 512u, u_w + (size_t)idx * 32 + lane, pol_keep);
        }
        {
            int pidx = __ldg(pos_w + b);
            cp_async16(dst0 + 10 * 512u, w_w + (size_t)pidx * 32 + lane, pol_stream);
        }
        #pragma unroll
        for (int k = 0; k < NEG; ++k) {
            int idx = __ldg(nw + k);
            cp_async16(dst0 + (11 + k) * 512u, w_w + (size_t)idx * 32 + lane, pol_stream);
        }
        cp_async_commit();
        cp_async_wait_all();

        // ---- accumulate from smem (each lane reads only its own bytes) ----
        float4 usum = make_float4(0.f, 0.f, 0.f, 0.f);
        #pragma unroll
        for (int c = 0; c < CTX; ++c) {
            float4 v = buf[warp][c][lane];
            usum.x += v.x; usum.y += v.y; usum.z += v.z; usum.w += v.w;
        }
        float4 p = buf[warp][10][lane];
        float pd = usum.x * p.x + usum.y * p.y + usum.z * p.z + usum.w * p.w;

        float4 nsum = make_float4(0.f, 0.f, 0.f, 0.f);
        #pragma unroll
        for (int k = 0; k < NEG; ++k) {
            float4 v = buf[warp][11 + k][lane];
            nsum.x += v.x; nsum.y += v.y; nsum.z += v.z; nsum.w += v.w;
        }
        float nd = usum.x * nsum.x + usum.y * nsum.y + usum.z * nsum.z + usum.w * nsum.w;

        // ---- warp reduce both dots together ----
        #pragma unroll
        for (int off = 16; off > 0; off >>= 1) {
            pd += __shfl_xor_sync(0xFFFFFFFFu, pd, off);
            nd += __shfl_xor_sync(0xFFFFFFFFu, nd, off);
        }
        if (lane == 0)
            ls += log_sigmoid(pd) + log_sigmoid(-nd);
    }

    __shared__ float s_part[WARPS_PER_BLOCK];
    if (lane == 0)
        s_part[warp] = ls;
    __syncthreads();

    // --- featherweight epilogue: one double atomic per block + ticket ---
    if (threadIdx.x == 0) {
        float acc = 0.f;
        #pragma unroll
        for (int i = 0; i < WARPS_PER_BLOCK; ++i) acc += s_part[i];
        atomicAdd(&g_accum, (double)acc);   // order-insensitive in double
        __threadfence();                    // release before ticket
        unsigned int t = atomicAdd(&g_ticket, 1u);
        if (t == NUM_BLOCKS - 1) {
            __threadfence();                // acquire after last ticket
            double total = g_accum;
            out[0] = (float)(-total);       // loss = -(sum of logsigmoids)
            g_accum  = 0.0;                 // reset for next graph replay
            g_ticket = 0;
        }
    }
}

extern "C" void kernel_launch(void* const* d_in, const int* in_sizes, int n_in,
                              void* d_out, int out_size) {
    const int*    pos_u = (const int*)d_in[0];
    const int*    pos_w = (const int*)d_in[1];
    const int*    neg_w = (const int*)d_in[2];
    const float4* u_w   = (const float4*)d_in[3];
    const float4* w_w   = (const float4*)d_in[4];
    float* out = (float*)d_out;

    cbow_loss_fused<<<NUM_BLOCKS, THREADS>>>(pos_u, pos_w, neg_w, u_w, w_w, out);
}